// round 2
// baseline (speedup 1.0000x reference)
#include <cuda_runtime.h>
#include <cstdint>

// ---------------------------------------------------------------------------
// Problem constants
// ---------------------------------------------------------------------------
#define HIDDEN   2048
#define N_HEADS  32
#define N_KV     8
#define HEAD_DIM 64
#define GROUP    4
#define FFN      8192
#define SEQ      1024
#define BATCH    2
#define NTOK     (BATCH * SEQ)          // 2048 tokens
#define KV_DIM   (N_KV * HEAD_DIM)      // 512

// ---------------------------------------------------------------------------
// Scratch (device globals: allocation-free rule)
// ---------------------------------------------------------------------------
__device__ float g_normed[NTOK * HIDDEN];
__device__ float g_q     [NTOK * HIDDEN];
__device__ float g_k     [NTOK * KV_DIM];
__device__ float g_v     [NTOK * KV_DIM];
__device__ float g_ctx   [NTOK * HIDDEN];
__device__ float g_attn  [NTOK * HIDDEN];
__device__ float g_sum   [NTOK * HIDDEN];
__device__ float g_gate  [NTOK * FFN];
__device__ float g_h     [NTOK * FFN];

// ---------------------------------------------------------------------------
// Packed f32x2 helpers (Blackwell sm_100a): 2 FMAs per instruction
// ---------------------------------------------------------------------------
__device__ __forceinline__ unsigned long long pk2(float x, float y) {
    unsigned long long r;
    asm("mov.b64 %0, {%1, %2};" : "=l"(r) : "f"(x), "f"(y));
    return r;
}
__device__ __forceinline__ float2 upk2(unsigned long long a) {
    float2 r;
    asm("mov.b64 {%0, %1}, %2;" : "=f"(r.x), "=f"(r.y) : "l"(a));
    return r;
}
__device__ __forceinline__ unsigned long long fma2(unsigned long long a,
                                                   unsigned long long b,
                                                   unsigned long long c) {
    unsigned long long d;
    asm("fma.rn.f32x2 %0, %1, %2, %3;" : "=l"(d) : "l"(a), "l"(b), "l"(c));
    return d;
}
__device__ __forceinline__ unsigned long long mul2(unsigned long long a,
                                                   unsigned long long b) {
    unsigned long long d;
    asm("mul.rn.f32x2 %0, %1, %2;" : "=l"(d) : "l"(a), "l"(b));
    return d;
}

__device__ __forceinline__ float silu_f(float x) {
    return x / (1.0f + __expf(-x));
}

// ---------------------------------------------------------------------------
// RMSNorm: one block per row of 2048
// ---------------------------------------------------------------------------
__global__ __launch_bounds__(256) void rmsnorm_k(const float* __restrict__ x,
                                                 const float* __restrict__ w,
                                                 float* __restrict__ o) {
    int row = blockIdx.x;
    int tid = threadIdx.x;
    const float* xr = x + (size_t)row * HIDDEN;
    float4 v0 = *(const float4*)(xr + tid * 4);
    float4 v1 = *(const float4*)(xr + 1024 + tid * 4);
    float ss = v0.x * v0.x + v0.y * v0.y + v0.z * v0.z + v0.w * v0.w
             + v1.x * v1.x + v1.y * v1.y + v1.z * v1.z + v1.w * v1.w;
    __shared__ float red[256];
    red[tid] = ss;
    __syncthreads();
    for (int s = 128; s > 0; s >>= 1) {
        if (tid < s) red[tid] += red[tid + s];
        __syncthreads();
    }
    float scale = rsqrtf(red[0] * (1.0f / HIDDEN) + 1e-5f);
    float4 w0 = *(const float4*)(w + tid * 4);
    float4 w1 = *(const float4*)(w + 1024 + tid * 4);
    float* orow = o + (size_t)row * HIDDEN;
    float4 o0, o1;
    o0.x = v0.x * scale * w0.x; o0.y = v0.y * scale * w0.y;
    o0.z = v0.z * scale * w0.z; o0.w = v0.w * scale * w0.w;
    o1.x = v1.x * scale * w1.x; o1.y = v1.y * scale * w1.y;
    o1.z = v1.z * scale * w1.z; o1.w = v1.w * scale * w1.w;
    *(float4*)(orow + tid * 4) = o0;
    *(float4*)(orow + 1024 + tid * 4) = o1;
}

// ---------------------------------------------------------------------------
// Generic fp32 GEMM: C[M,N] = A[M,K] @ B[K,N], all row-major.
// 128x128x16 tile, 256 threads, 8x8 per thread, f32x2 FMAs,
// register-prefetch double buffering.
// mode 0: C = acc
// mode 1: C = acc ; D = acc + E          (O-proj: attn_out + residual sum)
// mode 2: C = acc + E                    (down-proj: + attn_out)
// mode 3: C = silu(E) * acc              (up-proj fused with gate buffer)
// ---------------------------------------------------------------------------
__global__ __launch_bounds__(256) void gemm_f32(const float* __restrict__ A,
                                                const float* __restrict__ B,
                                                float* __restrict__ C,
                                                int M, int N, int K,
                                                int mode,
                                                float* __restrict__ D,
                                                const float* __restrict__ E) {
    __shared__ float Ast[16][132];   // A tile transposed [k][m], padded
    __shared__ float Bs [16][128];   // B tile [k][n]

    const int tid = threadIdx.x;
    const int tr = tid >> 4;         // 0..15 (row group)
    const int tc = tid & 15;         // 0..15 (col group)
    const int row0 = blockIdx.y * 128;
    const int col0 = blockIdx.x * 128;

    // global load mapping
    const int aLr = tid >> 2;              // 0..63 (+64 second phase)
    const int aLc = (tid & 3) * 4;         // 0,4,8,12
    const int bLr = tid >> 5;              // 0..7  (+8 second phase)
    const int bLc = (tid & 31) * 4;        // 0..124

    const float* Aptr = A + (size_t)(row0 + aLr) * K + aLc;
    const float* Bptr = B + (size_t)bLr * N + col0 + bLc;

    unsigned long long acc[8][4];
    #pragma unroll
    for (int i = 0; i < 8; i++)
        #pragma unroll
        for (int j = 0; j < 4; j++) acc[i][j] = 0ull;

    float4 pa0 = *(const float4*)(Aptr);
    float4 pa1 = *(const float4*)(Aptr + (size_t)64 * K);
    float4 pb0 = *(const float4*)(Bptr);
    float4 pb1 = *(const float4*)(Bptr + (size_t)8 * N);

    const int nk = K >> 4;
    for (int kt = 0; kt < nk; kt++) {
        // commit prefetched tile to smem
        Ast[aLc + 0][aLr] = pa0.x; Ast[aLc + 1][aLr] = pa0.y;
        Ast[aLc + 2][aLr] = pa0.z; Ast[aLc + 3][aLr] = pa0.w;
        Ast[aLc + 0][aLr + 64] = pa1.x; Ast[aLc + 1][aLr + 64] = pa1.y;
        Ast[aLc + 2][aLr + 64] = pa1.z; Ast[aLc + 3][aLr + 64] = pa1.w;
        *(float4*)&Bs[bLr][bLc]     = pb0;
        *(float4*)&Bs[bLr + 8][bLc] = pb1;
        __syncthreads();

        if (kt + 1 < nk) {
            const float* An = Aptr + (kt + 1) * 16;
            const float* Bn = Bptr + (size_t)(kt + 1) * 16 * N;
            pa0 = *(const float4*)(An);
            pa1 = *(const float4*)(An + (size_t)64 * K);
            pb0 = *(const float4*)(Bn);
            pb1 = *(const float4*)(Bn + (size_t)8 * N);
        }

        #pragma unroll
        for (int k = 0; k < 16; k++) {
            float4 a0 = *(const float4*)&Ast[k][tr * 8];
            float4 a1 = *(const float4*)&Ast[k][tr * 8 + 4];
            ulonglong2 bq0 = *(const ulonglong2*)&Bs[k][tc * 8];
            ulonglong2 bq1 = *(const ulonglong2*)&Bs[k][tc * 8 + 4];
            float av[8] = {a0.x, a0.y, a0.z, a0.w, a1.x, a1.y, a1.z, a1.w};
            #pragma unroll
            for (int i = 0; i < 8; i++) {
                unsigned long long ad = pk2(av[i], av[i]);
                acc[i][0] = fma2(ad, bq0.x, acc[i][0]);
                acc[i][1] = fma2(ad, bq0.y, acc[i][1]);
                acc[i][2] = fma2(ad, bq1.x, acc[i][2]);
                acc[i][3] = fma2(ad, bq1.y, acc[i][3]);
            }
        }
        __syncthreads();
    }

    // epilogue
    #pragma unroll
    for (int i = 0; i < 8; i++) {
        int r = row0 + tr * 8 + i;
        #pragma unroll
        for (int j = 0; j < 4; j++) {
            int c = col0 + tc * 8 + j * 2;
            size_t idx = (size_t)r * N + c;
            float2 val = upk2(acc[i][j]);
            if (mode == 0) {
                *(float2*)&C[idx] = val;
            } else if (mode == 1) {
                *(float2*)&C[idx] = val;
                float2 e = *(const float2*)&E[idx];
                float2 d2 = {val.x + e.x, val.y + e.y};
                *(float2*)&D[idx] = d2;
            } else if (mode == 2) {
                float2 e = *(const float2*)&E[idx];
                float2 d2 = {val.x + e.x, val.y + e.y};
                *(float2*)&C[idx] = d2;
            } else {
                float2 g = *(const float2*)&E[idx];
                float2 d2 = {silu_f(g.x) * val.x, silu_f(g.y) * val.y};
                *(float2*)&C[idx] = d2;
            }
        }
    }
}

// ---------------------------------------------------------------------------
// RoPE (in place on q and k). One thread per (token, freq-index i<32),
// double-precision angle/sincos so -use_fast_math cannot break range
// reduction at pos up to 1023 rad.
// ---------------------------------------------------------------------------
__global__ void rope_k(float* __restrict__ q, float* __restrict__ k,
                       const int* __restrict__ pos_ids) {
    int gid = blockIdx.x * blockDim.x + threadIdx.x;
    if (gid >= NTOK * 32) return;
    int i = gid & 31;
    int t = gid >> 5;
    int pos = pos_ids[t];
    double inv = pow(500000.0, -((double)(2 * i)) / 64.0);
    double sd, cd;
    sincos((double)pos * inv, &sd, &cd);
    float c = (float)cd, s = (float)sd;
    float* qrow = q + (size_t)t * HIDDEN;
    #pragma unroll 4
    for (int h = 0; h < N_HEADS; h++) {
        float* b = qrow + h * HEAD_DIM;
        float x0 = b[i], x1 = b[i + 32];
        b[i]      = x0 * c - x1 * s;
        b[i + 32] = x1 * c + x0 * s;
    }
    float* krow = k + (size_t)t * KV_DIM;
    #pragma unroll 4
    for (int h = 0; h < N_KV; h++) {
        float* b = krow + h * HEAD_DIM;
        float x0 = b[i], x1 = b[i + 32];
        b[i]      = x0 * c - x1 * s;
        b[i + 32] = x1 * c + x0 * s;
    }
}

// ---------------------------------------------------------------------------
// Flash attention, fp32, causal, GQA (4 q-heads per kv head).
// Block: 256 threads handles one (b,h, 64-row q tile); iterates 64-col kv
// tiles. Online softmax (4 threads per row, warp shuffles).
// S and PV GEMMs use f32x2.
// Dynamic smem: Qs^T, Ks^T, Vs, Ss each [64][68] + m/l/corr.
// ---------------------------------------------------------------------------
#define ATTN_SMEM_FLOATS (4 * 64 * 68 + 192)
#define ATTN_SMEM_BYTES  (ATTN_SMEM_FLOATS * 4)

__global__ __launch_bounds__(256) void attn_k(const float* __restrict__ q,
                                              const float* __restrict__ k,
                                              const float* __restrict__ v,
                                              float* __restrict__ ctx) {
    extern __shared__ float sm[];
    float* Qs = sm;                 // [d][r], stride 68
    float* Ks = sm + 4352;          // [d][c], stride 68
    float* Vs = sm + 8704;          // [c][d], stride 68
    float* Ss = sm + 13056;         // [r][c], stride 68
    float* m_s  = sm + 17408;
    float* l_s  = sm + 17472;
    float* cr_s = sm + 17536;

    const int qt = blockIdx.x;       // q tile 0..15
    const int bh = blockIdx.y;       // 0..63
    const int b   = bh >> 5;
    const int h   = bh & 31;
    const int kvh = h >> 2;
    const int tid = threadIdx.x;
    const int tr = tid >> 4;         // 0..15 -> rows tr*4..+3
    const int tc = tid & 15;         // 0..15 -> cols tc*4..+3
    const int qbase = b * SEQ + qt * 64;

    // load Q tile (transposed, pre-scaled by 1/sqrt(64))
    for (int lin = tid; lin < 1024; lin += 256) {
        int r  = lin >> 4;
        int d4 = (lin & 15) << 2;
        float4 f = *(const float4*)&q[(size_t)(qbase + r) * HIDDEN + h * HEAD_DIM + d4];
        Qs[(d4 + 0) * 68 + r] = f.x * 0.125f;
        Qs[(d4 + 1) * 68 + r] = f.y * 0.125f;
        Qs[(d4 + 2) * 68 + r] = f.z * 0.125f;
        Qs[(d4 + 3) * 68 + r] = f.w * 0.125f;
    }
    if (tid < 64) { m_s[tid] = -1e30f; l_s[tid] = 0.0f; }

    unsigned long long o2[4][2];
    #pragma unroll
    for (int i = 0; i < 4; i++) { o2[i][0] = 0ull; o2[i][1] = 0ull; }

    __syncthreads();

    for (int kt = 0; kt <= qt; kt++) {
        const int kbase = b * SEQ + kt * 64;
        // load K (transposed) and V tiles
        for (int lin = tid; lin < 1024; lin += 256) {
            int c  = lin >> 4;
            int d4 = (lin & 15) << 2;
            size_t gi = (size_t)(kbase + c) * KV_DIM + kvh * HEAD_DIM + d4;
            float4 kf = *(const float4*)&k[gi];
            Ks[(d4 + 0) * 68 + c] = kf.x;
            Ks[(d4 + 1) * 68 + c] = kf.y;
            Ks[(d4 + 2) * 68 + c] = kf.z;
            Ks[(d4 + 3) * 68 + c] = kf.w;
            float4 vf = *(const float4*)&v[gi];
            *(float4*)&Vs[c * 68 + d4] = vf;
        }
        __syncthreads();

        // S = Q K^T  (4x4 tile per thread)
        unsigned long long s2[4][2];
        #pragma unroll
        for (int i = 0; i < 4; i++) { s2[i][0] = 0ull; s2[i][1] = 0ull; }
        #pragma unroll 8
        for (int d = 0; d < 64; d++) {
            float4 a4 = *(const float4*)&Qs[d * 68 + tr * 4];
            float4 b4 = *(const float4*)&Ks[d * 68 + tc * 4];
            unsigned long long blo = pk2(b4.x, b4.y);
            unsigned long long bhi = pk2(b4.z, b4.w);
            float avv[4] = {a4.x, a4.y, a4.z, a4.w};
            #pragma unroll
            for (int i = 0; i < 4; i++) {
                unsigned long long ad = pk2(avv[i], avv[i]);
                s2[i][0] = fma2(ad, blo, s2[i][0]);
                s2[i][1] = fma2(ad, bhi, s2[i][1]);
            }
        }
        // write S with causal mask (only the diagonal tile needs it)
        bool diag = (kt == qt);
        #pragma unroll
        for (int i = 0; i < 4; i++) {
            int lr = tr * 4 + i;
            #pragma unroll
            for (int jp = 0; jp < 2; jp++) {
                int lc = tc * 4 + jp * 2;
                float2 vv = upk2(s2[i][jp]);
                Ss[lr * 68 + lc]     = (!diag || lr >= lc)     ? vv.x : -1e30f;
                Ss[lr * 68 + lc + 1] = (!diag || lr >= lc + 1) ? vv.y : -1e30f;
            }
        }
        __syncthreads();

        // online softmax: 4 threads per row (lane-aligned), shuffles to reduce
        {
            int r = tid >> 2;
            int sub = tid & 3;
            float* row = Ss + r * 68 + sub * 16;
            float mo = m_s[r];
            float mx = mo;
            #pragma unroll
            for (int j = 0; j < 16; j++) mx = fmaxf(mx, row[j]);
            mx = fmaxf(mx, __shfl_xor_sync(0xffffffffu, mx, 1));
            mx = fmaxf(mx, __shfl_xor_sync(0xffffffffu, mx, 2));
            float lsum = 0.0f;
            #pragma unroll
            for (int j = 0; j < 16; j++) {
                float e = __expf(row[j] - mx);
                row[j] = e;
                lsum += e;
            }
            lsum += __shfl_xor_sync(0xffffffffu, lsum, 1);
            lsum += __shfl_xor_sync(0xffffffffu, lsum, 2);
            if (sub == 0) {
                float co = __expf(mo - mx);
                l_s[r] = l_s[r] * co + lsum;
                m_s[r] = mx;
                cr_s[r] = co;
            }
        }
        __syncthreads();

        // O = O*corr + P @ V
        #pragma unroll
        for (int i = 0; i < 4; i++) {
            float co = cr_s[tr * 4 + i];
            unsigned long long co2 = pk2(co, co);
            o2[i][0] = mul2(o2[i][0], co2);
            o2[i][1] = mul2(o2[i][1], co2);
        }
        #pragma unroll 8
        for (int c = 0; c < 64; c++) {
            float4 v4 = *(const float4*)&Vs[c * 68 + tc * 4];
            unsigned long long vlo = pk2(v4.x, v4.y);
            unsigned long long vhi = pk2(v4.z, v4.w);
            #pragma unroll
            for (int i = 0; i < 4; i++) {
                float p = Ss[(tr * 4 + i) * 68 + c];
                unsigned long long pd = pk2(p, p);
                o2[i][0] = fma2(pd, vlo, o2[i][0]);
                o2[i][1] = fma2(pd, vhi, o2[i][1]);
            }
        }
        __syncthreads();
    }

    // write ctx = O / l
    #pragma unroll
    for (int i = 0; i < 4; i++) {
        int lr = tr * 4 + i;
        float inv = 1.0f / l_s[lr];
        size_t orow = (size_t)(qbase + lr) * HIDDEN + h * HEAD_DIM + tc * 4;
        float2 a = upk2(o2[i][0]);
        float2 bb = upk2(o2[i][1]);
        float2 w0 = {a.x * inv, a.y * inv};
        float2 w1 = {bb.x * inv, bb.y * inv};
        *(float2*)&ctx[orow]     = w0;
        *(float2*)&ctx[orow + 2] = w1;
    }
}

// ---------------------------------------------------------------------------
// Launch
// Input order: hidden_states, attention_mask, wq, wk, wv, wo, norm1_w,
//              norm2_w, w_gate, w_up, w_down, position_ids
// ---------------------------------------------------------------------------
extern "C" void kernel_launch(void* const* d_in, const int* in_sizes, int n_in,
                              void* d_out, int out_size) {
    const float* hidden = (const float*)d_in[0];
    const float* wq = (const float*)d_in[2];
    const float* wk = (const float*)d_in[3];
    const float* wv = (const float*)d_in[4];
    const float* wo = (const float*)d_in[5];
    const float* n1 = (const float*)d_in[6];
    const float* n2 = (const float*)d_in[7];
    const float* wg = (const float*)d_in[8];
    const float* wu = (const float*)d_in[9];
    const float* wd = (const float*)d_in[10];
    const int* pos = (const int*)d_in[11];
    float* out = (float*)d_out;

    float *normed, *q, *k, *v, *ctx, *attn, *sum, *gate, *hbuf;
    cudaGetSymbolAddress((void**)&normed, g_normed);
    cudaGetSymbolAddress((void**)&q,      g_q);
    cudaGetSymbolAddress((void**)&k,      g_k);
    cudaGetSymbolAddress((void**)&v,      g_v);
    cudaGetSymbolAddress((void**)&ctx,    g_ctx);
    cudaGetSymbolAddress((void**)&attn,   g_attn);
    cudaGetSymbolAddress((void**)&sum,    g_sum);
    cudaGetSymbolAddress((void**)&gate,   g_gate);
    cudaGetSymbolAddress((void**)&hbuf,   g_h);

    // norm1
    rmsnorm_k<<<NTOK, 256>>>(hidden, n1, normed);
    // QKV projections
    gemm_f32<<<dim3(HIDDEN / 128, NTOK / 128), 256>>>(normed, wq, q, NTOK, HIDDEN, HIDDEN, 0, nullptr, nullptr);
    gemm_f32<<<dim3(KV_DIM / 128, NTOK / 128), 256>>>(normed, wk, k, NTOK, KV_DIM, HIDDEN, 0, nullptr, nullptr);
    gemm_f32<<<dim3(KV_DIM / 128, NTOK / 128), 256>>>(normed, wv, v, NTOK, KV_DIM, HIDDEN, 0, nullptr, nullptr);
    // RoPE
    rope_k<<<(NTOK * 32 + 255) / 256, 256>>>(q, k, pos);
    // attention
    cudaFuncSetAttribute(attn_k, cudaFuncAttributeMaxDynamicSharedMemorySize, ATTN_SMEM_BYTES);
    attn_k<<<dim3(SEQ / 64, BATCH * N_HEADS), 256, ATTN_SMEM_BYTES>>>(q, k, v, ctx);
    // O proj: attn = ctx@wo ; sum = attn + hidden
    gemm_f32<<<dim3(HIDDEN / 128, NTOK / 128), 256>>>(ctx, wo, attn, NTOK, HIDDEN, HIDDEN, 1, sum, hidden);
    // norm2 (reuse normed buffer)
    rmsnorm_k<<<NTOK, 256>>>(sum, n2, normed);
    // MLP: gate, then up fused with silu(gate)*up, then down fused with +attn
    gemm_f32<<<dim3(FFN / 128, NTOK / 128), 256>>>(normed, wg, gate, NTOK, FFN, HIDDEN, 0, nullptr, nullptr);
    gemm_f32<<<dim3(FFN / 128, NTOK / 128), 256>>>(normed, wu, hbuf, NTOK, FFN, HIDDEN, 3, nullptr, gate);
    gemm_f32<<<dim3(HIDDEN / 128, NTOK / 128), 256>>>(hbuf, wd, out, NTOK, HIDDEN, FFN, 2, nullptr, attn);
}

// round 5
// speedup vs baseline: 1.7739x; 1.7739x over previous
#include <cuda_runtime.h>
#include <cuda_bf16.h>
#include <cstdint>

// ---------------------------------------------------------------------------
// Problem constants
// ---------------------------------------------------------------------------
#define HIDDEN   2048
#define N_HEADS  32
#define N_KV     8
#define HEAD_DIM 64
#define FFN      8192
#define SEQ      1024
#define BATCH    2
#define NTOK     (BATCH * SEQ)          // 2048 tokens
#define QKV_DIM  3072                   // 2048 q + 512 k + 512 v
#define GU_DIM   16384                  // 8192 gate + 8192 up

// ---------------------------------------------------------------------------
// Scratch (device globals: allocation-free rule)
// ---------------------------------------------------------------------------
__device__ float g_qkv [NTOK * QKV_DIM];
__device__ float g_ctx [NTOK * HIDDEN];
__device__ float g_attn[NTOK * HIDDEN];
__device__ float g_sum [NTOK * HIDDEN];
__device__ float g_gu  [NTOK * GU_DIM];
__device__ __nv_bfloat16 g_ah[NTOK * HIDDEN],   g_al[NTOK * HIDDEN];
__device__ __nv_bfloat16 g_ctxh[NTOK * HIDDEN], g_ctxl[NTOK * HIDDEN];
__device__ __nv_bfloat16 g_hh[NTOK * FFN],      g_hl[NTOK * FFN];
__device__ __nv_bfloat16 g_wqkvh[QKV_DIM * HIDDEN], g_wqkvl[QKV_DIM * HIDDEN];
__device__ __nv_bfloat16 g_woh [HIDDEN * HIDDEN],   g_wol [HIDDEN * HIDDEN];
__device__ __nv_bfloat16 g_wguh[GU_DIM * HIDDEN],   g_wgul[GU_DIM * HIDDEN];
__device__ __nv_bfloat16 g_wdh [HIDDEN * FFN],      g_wdl [HIDDEN * FFN];

// ---------------------------------------------------------------------------
// Helpers
// ---------------------------------------------------------------------------
__device__ __forceinline__ uint32_t smem_u32(const void* p) {
    uint32_t a;
    asm("{ .reg .u64 t; cvta.to.shared.u64 t, %1; cvt.u32.u64 %0, t; }" : "=r"(a) : "l"(p));
    return a;
}
__device__ __forceinline__ void cpa16(uint32_t dst, const void* src) {
    asm volatile("cp.async.cg.shared.global [%0], [%1], 16;" :: "r"(dst), "l"(src));
}
__device__ __forceinline__ void ldm4(uint32_t* r, uint32_t addr) {
    asm volatile("ldmatrix.sync.aligned.m8n8.x4.shared.b16 {%0,%1,%2,%3}, [%4];"
        : "=r"(r[0]), "=r"(r[1]), "=r"(r[2]), "=r"(r[3]) : "r"(addr));
}
__device__ __forceinline__ void mma_bf16(float* c, const uint32_t* a,
                                         uint32_t b0, uint32_t b1) {
    asm volatile("mma.sync.aligned.m16n8k16.row.col.f32.bf16.bf16.f32 "
        "{%0,%1,%2,%3}, {%4,%5,%6,%7}, {%8,%9}, {%0,%1,%2,%3};"
        : "+f"(c[0]), "+f"(c[1]), "+f"(c[2]), "+f"(c[3])
        : "r"(a[0]), "r"(a[1]), "r"(a[2]), "r"(a[3]), "r"(b0), "r"(b1));
}
__device__ __forceinline__ float silu_f(float x) { return x / (1.0f + __expf(-x)); }
__device__ __forceinline__ void split_bf16(float x, __nv_bfloat16& h, __nv_bfloat16& l) {
    h = __float2bfloat16(x);
    l = __float2bfloat16(x - __bfloat162float(h));
}
// f32x2 helpers (attention)
__device__ __forceinline__ unsigned long long pk2(float x, float y) {
    unsigned long long r; asm("mov.b64 %0, {%1, %2};" : "=l"(r) : "f"(x), "f"(y)); return r;
}
__device__ __forceinline__ float2 upk2(unsigned long long a) {
    float2 r; asm("mov.b64 {%0, %1}, %2;" : "=f"(r.x), "=f"(r.y) : "l"(a)); return r;
}
__device__ __forceinline__ unsigned long long fma2(unsigned long long a, unsigned long long b, unsigned long long c) {
    unsigned long long d; asm("fma.rn.f32x2 %0, %1, %2, %3;" : "=l"(d) : "l"(a), "l"(b), "l"(c)); return d;
}
__device__ __forceinline__ unsigned long long mul2(unsigned long long a, unsigned long long b) {
    unsigned long long d; asm("mul.rn.f32x2 %0, %1, %2;" : "=l"(d) : "l"(a), "l"(b)); return d;
}

// ---------------------------------------------------------------------------
// Tensor-core GEMM via mma.sync (sm_100-legal HMMA path)
// C[M,N] = A[M,K] @ B^T,  A/B given as bf16 hi/lo pairs, B stored [N,K].
// 3-term split: Ah*Bh + Ah*Bl + Al*Bh, fp32 accumulate.
// Tile 128x128x32, 8 warps (4 M x 2 N), warp tile 32x64, 2-stage cp.async.
// mode 0: C = acc ; mode 1: C = acc, D = acc + E ; mode 2: C = acc + E
// ---------------------------------------------------------------------------
#define ROWB 80                       // smem bytes per 32-elem bf16 row (64 + 16 pad)
#define MAT_BYTES (128 * ROWB)        // 10240
#define STAGE_BYTES (4 * MAT_BYTES)   // 40960 (Ah, Al, Bh, Bl)
#define GEMM_SMEM (2 * STAGE_BYTES)   // 81920

__global__ __launch_bounds__(256, 1) void gemm_mma(
    const __nv_bfloat16* __restrict__ Ah, const __nv_bfloat16* __restrict__ Al,
    const __nv_bfloat16* __restrict__ Bh, const __nv_bfloat16* __restrict__ Bl,
    float* __restrict__ C, int K, int Nout, int mode,
    float* __restrict__ D, const float* __restrict__ E)
{
    extern __shared__ char smem_[];
    const uint32_t sb = smem_u32(smem_);
    const int tid = threadIdx.x, wid = tid >> 5, lane = tid & 31;
    const int warp_m = wid & 3, warp_n = wid >> 2;
    const int row0 = blockIdx.y * 128;
    const int n0   = blockIdx.x * 128;

    float acc[2][8][4];
    #pragma unroll
    for (int i = 0; i < 2; i++)
        #pragma unroll
        for (int j = 0; j < 8; j++)
            #pragma unroll
            for (int t = 0; t < 4; t++) acc[i][j][t] = 0.0f;

    // global load positions: 128 rows x 4 x 16B segments per matrix
    const int gr  = tid >> 2;          // rows gr, gr+64
    const int seg = tid & 3;

    auto load_stage = [&](int ch) {
        const uint32_t st = sb + (ch & 1) * STAGE_BYTES;
        const int k0 = ch * 32;
        #pragma unroll
        for (int i = 0; i < 2; i++) {
            int r = gr + i * 64;
            uint32_t dst = (uint32_t)(r * ROWB + seg * 16);
            size_t goA = (size_t)(row0 + r) * K + k0 + seg * 8;
            size_t goB = (size_t)(n0 + r) * K + k0 + seg * 8;
            cpa16(st + dst,                 Ah + goA);
            cpa16(st + MAT_BYTES + dst,     Al + goA);
            cpa16(st + 2*MAT_BYTES + dst,   Bh + goB);
            cpa16(st + 3*MAT_BYTES + dst,   Bl + goB);
        }
        asm volatile("cp.async.commit_group;" ::: "memory");
    };

    const int nch = K / 32;
    load_stage(0);

    for (int ch = 0; ch < nch; ch++) {
        if (ch + 1 < nch) {
            load_stage(ch + 1);
            asm volatile("cp.async.wait_group 1;" ::: "memory");
        } else {
            asm volatile("cp.async.wait_group 0;" ::: "memory");
        }
        __syncthreads();

        const uint32_t st = sb + (ch & 1) * STAGE_BYTES;
        // ldmatrix base addresses: rows (lane&15), k-half (lane>>4)*8 elems
        const uint32_t a_base = st +
            (uint32_t)((warp_m * 32 + (lane & 15)) * ROWB + ((lane >> 4) * 8) * 2);
        const uint32_t b_base = st + 2*MAT_BYTES +
            (uint32_t)((warp_n * 64 + (lane & 15)) * ROWB + ((lane >> 4) * 8) * 2);

        #pragma unroll
        for (int ks = 0; ks < 2; ks++) {
            const uint32_t koff = ks * 32;   // 16 bf16 = 32 bytes
            uint32_t ahf[2][4], alf[2][4], bhf[4][4], blf[4][4];
            #pragma unroll
            for (int mt = 0; mt < 2; mt++) {
                ldm4(ahf[mt], a_base + mt * 16 * ROWB + koff);
                ldm4(alf[mt], a_base + MAT_BYTES + mt * 16 * ROWB + koff);
            }
            #pragma unroll
            for (int bt = 0; bt < 4; bt++) {
                ldm4(bhf[bt], b_base + bt * 16 * ROWB + koff);
                ldm4(blf[bt], b_base + MAT_BYTES + bt * 16 * ROWB + koff);
            }
            #pragma unroll
            for (int mt = 0; mt < 2; mt++) {
                #pragma unroll
                for (int bt = 0; bt < 4; bt++) {
                    // n-tile 2*bt uses regs {0,2}; n-tile 2*bt+1 uses {1,3}
                    mma_bf16(acc[mt][2*bt],   ahf[mt], bhf[bt][0], bhf[bt][2]);
                    mma_bf16(acc[mt][2*bt+1], ahf[mt], bhf[bt][1], bhf[bt][3]);
                    mma_bf16(acc[mt][2*bt],   ahf[mt], blf[bt][0], blf[bt][2]);
                    mma_bf16(acc[mt][2*bt+1], ahf[mt], blf[bt][1], blf[bt][3]);
                    mma_bf16(acc[mt][2*bt],   alf[mt], bhf[bt][0], bhf[bt][2]);
                    mma_bf16(acc[mt][2*bt+1], alf[mt], bhf[bt][1], bhf[bt][3]);
                }
            }
        }
        __syncthreads();
    }

    // epilogue: fragment (row = lane/4 [+8], col = (lane%4)*2)
    #pragma unroll
    for (int mt = 0; mt < 2; mt++) {
        #pragma unroll
        for (int nt = 0; nt < 8; nt++) {
            int r = row0 + warp_m * 32 + mt * 16 + (lane >> 2);
            int c = n0 + warp_n * 64 + nt * 8 + (lane & 3) * 2;
            #pragma unroll
            for (int half = 0; half < 2; half++) {
                int rr = r + half * 8;
                size_t idx = (size_t)rr * Nout + c;
                float2 v = make_float2(acc[mt][nt][half*2], acc[mt][nt][half*2+1]);
                if (mode == 0) {
                    *(float2*)&C[idx] = v;
                } else if (mode == 1) {
                    *(float2*)&C[idx] = v;
                    float2 e = *(const float2*)&E[idx];
                    *(float2*)&D[idx] = make_float2(v.x + e.x, v.y + e.y);
                } else {
                    float2 e = *(const float2*)&E[idx];
                    *(float2*)&C[idx] = make_float2(v.x + e.x, v.y + e.y);
                }
            }
        }
    }
}

// ---------------------------------------------------------------------------
// Weight transpose + bf16 hi/lo split: src[K,N] fp32 -> dst[N,K] bf16 x2
// ---------------------------------------------------------------------------
__global__ __launch_bounds__(256) void wconv_k(const float* __restrict__ src,
                                               __nv_bfloat16* __restrict__ dh,
                                               __nv_bfloat16* __restrict__ dl,
                                               int K, int N) {
    __shared__ float t[32][33];
    const int n0 = blockIdx.x * 32, k0 = blockIdx.y * 32;
    const int tx = threadIdx.x & 31, ty = threadIdx.x >> 5;
    #pragma unroll
    for (int j = 0; j < 32; j += 8)
        t[ty + j][tx] = src[(size_t)(k0 + ty + j) * N + n0 + tx];
    __syncthreads();
    #pragma unroll
    for (int j = 0; j < 32; j += 8) {
        float x = t[tx][ty + j];
        __nv_bfloat16 h, l; split_bf16(x, h, l);
        size_t o = (size_t)(n0 + ty + j) * K + k0 + tx;
        dh[o] = h; dl[o] = l;
    }
}

// ---------------------------------------------------------------------------
// RMSNorm -> bf16 hi/lo split output
// ---------------------------------------------------------------------------
__global__ __launch_bounds__(256) void rmsnorm_bf16(const float* __restrict__ x,
                                                    const float* __restrict__ w,
                                                    __nv_bfloat16* __restrict__ oh,
                                                    __nv_bfloat16* __restrict__ ol) {
    const int row = blockIdx.x, tid = threadIdx.x;
    const float* xr = x + (size_t)row * HIDDEN;
    float4 v0 = *(const float4*)(xr + tid * 4);
    float4 v1 = *(const float4*)(xr + 1024 + tid * 4);
    float ss = v0.x*v0.x + v0.y*v0.y + v0.z*v0.z + v0.w*v0.w
             + v1.x*v1.x + v1.y*v1.y + v1.z*v1.z + v1.w*v1.w;
    __shared__ float red[256];
    red[tid] = ss;
    __syncthreads();
    for (int s = 128; s > 0; s >>= 1) { if (tid < s) red[tid] += red[tid + s]; __syncthreads(); }
    float scale = rsqrtf(red[0] * (1.0f / HIDDEN) + 1e-5f);
    float4 w0 = *(const float4*)(w + tid * 4);
    float4 w1 = *(const float4*)(w + 1024 + tid * 4);
    size_t ob = (size_t)row * HIDDEN + tid * 4;
    float y[8] = {v0.x*scale*w0.x, v0.y*scale*w0.y, v0.z*scale*w0.z, v0.w*scale*w0.w,
                  v1.x*scale*w1.x, v1.y*scale*w1.y, v1.z*scale*w1.z, v1.w*scale*w1.w};
    #pragma unroll
    for (int i = 0; i < 4; i++) { __nv_bfloat16 h, l; split_bf16(y[i], h, l); oh[ob+i] = h; ol[ob+i] = l; }
    #pragma unroll
    for (int i = 0; i < 4; i++) { __nv_bfloat16 h, l; split_bf16(y[4+i], h, l); oh[ob+1024+i] = h; ol[ob+1024+i] = l; }
}

// elementwise fp32 -> bf16 hi/lo
__global__ void conv_bf16(const float* __restrict__ x, __nv_bfloat16* __restrict__ oh,
                          __nv_bfloat16* __restrict__ ol, int n) {
    int gid = blockIdx.x * blockDim.x + threadIdx.x;
    int i0 = gid * 4;
    if (i0 >= n) return;
    float4 v = *(const float4*)&x[i0];
    float y[4] = {v.x, v.y, v.z, v.w};
    #pragma unroll
    for (int i = 0; i < 4; i++) { __nv_bfloat16 h, l; split_bf16(y[i], h, l); oh[i0+i] = h; ol[i0+i] = l; }
}

// h = silu(gate) * up, output split to bf16 hi/lo
__global__ void silumul_k(const float* __restrict__ gu, __nv_bfloat16* __restrict__ hh,
                          __nv_bfloat16* __restrict__ hl) {
    int gid = blockIdx.x * blockDim.x + threadIdx.x;
    int lin = gid * 4;
    if (lin >= NTOK * FFN) return;
    int m = lin >> 13;
    int f = lin & 8191;
    float4 g = *(const float4*)&gu[(size_t)m * GU_DIM + f];
    float4 u = *(const float4*)&gu[(size_t)m * GU_DIM + 8192 + f];
    float y[4] = {silu_f(g.x)*u.x, silu_f(g.y)*u.y, silu_f(g.z)*u.z, silu_f(g.w)*u.w};
    size_t o = (size_t)m * FFN + f;
    #pragma unroll
    for (int i = 0; i < 4; i++) { __nv_bfloat16 h, l; split_bf16(y[i], h, l); hh[o+i] = h; hl[o+i] = l; }
}

// ---------------------------------------------------------------------------
// RoPE in place on fused qkv buffer (row stride 3072: q@0, k@2048)
// ---------------------------------------------------------------------------
__global__ void rope_k(float* __restrict__ qkv, const int* __restrict__ pos_ids) {
    int gid = blockIdx.x * blockDim.x + threadIdx.x;
    if (gid >= NTOK * 32) return;
    int i = gid & 31, t = gid >> 5;
    int pos = pos_ids[t];
    double inv = pow(500000.0, -((double)(2 * i)) / 64.0);
    double sd, cd;
    sincos((double)pos * inv, &sd, &cd);
    float c = (float)cd, s = (float)sd;
    float* row = qkv + (size_t)t * QKV_DIM;
    #pragma unroll 4
    for (int h = 0; h < N_HEADS; h++) {
        float* b = row + h * HEAD_DIM;
        float x0 = b[i], x1 = b[i + 32];
        b[i] = x0 * c - x1 * s;  b[i + 32] = x1 * c + x0 * s;
    }
    float* krow = row + 2048;
    #pragma unroll 4
    for (int h = 0; h < N_KV; h++) {
        float* b = krow + h * HEAD_DIM;
        float x0 = b[i], x1 = b[i + 32];
        b[i] = x0 * c - x1 * s;  b[i + 32] = x1 * c + x0 * s;
    }
}

// ---------------------------------------------------------------------------
// Flash attention, fp32, causal, GQA — reads fused qkv (stride 3072)
// ---------------------------------------------------------------------------
#define ATTN_SMEM_FLOATS (4 * 64 * 68 + 192)
#define ATTN_SMEM_BYTES  (ATTN_SMEM_FLOATS * 4)

__global__ __launch_bounds__(256) void attn_k(const float* __restrict__ qkv,
                                              float* __restrict__ ctx) {
    extern __shared__ float sm[];
    float* Qs = sm;
    float* Ks = sm + 4352;
    float* Vs = sm + 8704;
    float* Ss = sm + 13056;
    float* m_s  = sm + 17408;
    float* l_s  = sm + 17472;
    float* cr_s = sm + 17536;

    const int qt = blockIdx.x;
    const int bh = blockIdx.y;
    const int b = bh >> 5, h = bh & 31, kvh = h >> 2;
    const int tid = threadIdx.x;
    const int tr = tid >> 4, tc = tid & 15;
    const int qbase = b * SEQ + qt * 64;

    for (int lin = tid; lin < 1024; lin += 256) {
        int r = lin >> 4, d4 = (lin & 15) << 2;
        float4 f = *(const float4*)&qkv[(size_t)(qbase + r) * QKV_DIM + h * HEAD_DIM + d4];
        Qs[(d4+0)*68 + r] = f.x * 0.125f;
        Qs[(d4+1)*68 + r] = f.y * 0.125f;
        Qs[(d4+2)*68 + r] = f.z * 0.125f;
        Qs[(d4+3)*68 + r] = f.w * 0.125f;
    }
    if (tid < 64) { m_s[tid] = -1e30f; l_s[tid] = 0.0f; }

    unsigned long long o2[4][2];
    #pragma unroll
    for (int i = 0; i < 4; i++) { o2[i][0] = 0ull; o2[i][1] = 0ull; }
    __syncthreads();

    for (int kt = 0; kt <= qt; kt++) {
        const int kbase = b * SEQ + kt * 64;
        for (int lin = tid; lin < 1024; lin += 256) {
            int c = lin >> 4, d4 = (lin & 15) << 2;
            size_t gk = (size_t)(kbase + c) * QKV_DIM + 2048 + kvh * HEAD_DIM + d4;
            float4 kf = *(const float4*)&qkv[gk];
            Ks[(d4+0)*68 + c] = kf.x;
            Ks[(d4+1)*68 + c] = kf.y;
            Ks[(d4+2)*68 + c] = kf.z;
            Ks[(d4+3)*68 + c] = kf.w;
            float4 vf = *(const float4*)&qkv[gk + 512];
            *(float4*)&Vs[c*68 + d4] = vf;
        }
        __syncthreads();

        unsigned long long s2[4][2];
        #pragma unroll
        for (int i = 0; i < 4; i++) { s2[i][0] = 0ull; s2[i][1] = 0ull; }
        #pragma unroll 8
        for (int d = 0; d < 64; d++) {
            float4 a4 = *(const float4*)&Qs[d*68 + tr*4];
            float4 b4 = *(const float4*)&Ks[d*68 + tc*4];
            unsigned long long blo = pk2(b4.x, b4.y), bhi = pk2(b4.z, b4.w);
            float av[4] = {a4.x, a4.y, a4.z, a4.w};
            #pragma unroll
            for (int i = 0; i < 4; i++) {
                unsigned long long ad = pk2(av[i], av[i]);
                s2[i][0] = fma2(ad, blo, s2[i][0]);
                s2[i][1] = fma2(ad, bhi, s2[i][1]);
            }
        }
        bool diag = (kt == qt);
        #pragma unroll
        for (int i = 0; i < 4; i++) {
            int lr = tr*4 + i;
            #pragma unroll
            for (int jp = 0; jp < 2; jp++) {
                int lc = tc*4 + jp*2;
                float2 vv = upk2(s2[i][jp]);
                Ss[lr*68 + lc]     = (!diag || lr >= lc)     ? vv.x : -1e30f;
                Ss[lr*68 + lc + 1] = (!diag || lr >= lc + 1) ? vv.y : -1e30f;
            }
        }
        __syncthreads();

        {
            int r = tid >> 2, sub = tid & 3;
            float* row = Ss + r*68 + sub*16;
            float mo = m_s[r];
            float mx = mo;
            #pragma unroll
            for (int j = 0; j < 16; j++) mx = fmaxf(mx, row[j]);
            mx = fmaxf(mx, __shfl_xor_sync(0xffffffffu, mx, 1));
            mx = fmaxf(mx, __shfl_xor_sync(0xffffffffu, mx, 2));
            float lsum = 0.0f;
            #pragma unroll
            for (int j = 0; j < 16; j++) { float e = __expf(row[j] - mx); row[j] = e; lsum += e; }
            lsum += __shfl_xor_sync(0xffffffffu, lsum, 1);
            lsum += __shfl_xor_sync(0xffffffffu, lsum, 2);
            if (sub == 0) {
                float co = __expf(mo - mx);
                l_s[r] = l_s[r] * co + lsum;
                m_s[r] = mx;
                cr_s[r] = co;
            }
        }
        __syncthreads();

        #pragma unroll
        for (int i = 0; i < 4; i++) {
            float co = cr_s[tr*4 + i];
            unsigned long long co2 = pk2(co, co);
            o2[i][0] = mul2(o2[i][0], co2);
            o2[i][1] = mul2(o2[i][1], co2);
        }
        #pragma unroll 8
        for (int c = 0; c < 64; c++) {
            float4 v4 = *(const float4*)&Vs[c*68 + tc*4];
            unsigned long long vlo = pk2(v4.x, v4.y), vhi = pk2(v4.z, v4.w);
            #pragma unroll
            for (int i = 0; i < 4; i++) {
                float p = Ss[(tr*4 + i)*68 + c];
                unsigned long long pd = pk2(p, p);
                o2[i][0] = fma2(pd, vlo, o2[i][0]);
                o2[i][1] = fma2(pd, vhi, o2[i][1]);
            }
        }
        __syncthreads();
    }

    #pragma unroll
    for (int i = 0; i < 4; i++) {
        int lr = tr*4 + i;
        float inv = 1.0f / l_s[lr];
        size_t orow = (size_t)(qbase + lr) * HIDDEN + h * HEAD_DIM + tc * 4;
        float2 a = upk2(o2[i][0]);
        float2 bb = upk2(o2[i][1]);
        *(float2*)&ctx[orow]     = make_float2(a.x * inv, a.y * inv);
        *(float2*)&ctx[orow + 2] = make_float2(bb.x * inv, bb.y * inv);
    }
}

// ---------------------------------------------------------------------------
// Launch
// ---------------------------------------------------------------------------
extern "C" void kernel_launch(void* const* d_in, const int* in_sizes, int n_in,
                              void* d_out, int out_size) {
    const float* hidden = (const float*)d_in[0];
    const float* wq = (const float*)d_in[2];
    const float* wk = (const float*)d_in[3];
    const float* wv = (const float*)d_in[4];
    const float* wo = (const float*)d_in[5];
    const float* n1 = (const float*)d_in[6];
    const float* n2 = (const float*)d_in[7];
    const float* wg = (const float*)d_in[8];
    const float* wu = (const float*)d_in[9];
    const float* wd = (const float*)d_in[10];
    const int* pos  = (const int*)d_in[11];
    float* out = (float*)d_out;

    float *qkv, *ctx, *attn, *sum, *gu;
    __nv_bfloat16 *ah, *al, *ctxh, *ctxl, *hh, *hl;
    __nv_bfloat16 *wqkvh, *wqkvl, *woh, *wol, *wguh, *wgul, *wdh, *wdl;
    cudaGetSymbolAddress((void**)&qkv,  g_qkv);
    cudaGetSymbolAddress((void**)&ctx,  g_ctx);
    cudaGetSymbolAddress((void**)&attn, g_attn);
    cudaGetSymbolAddress((void**)&sum,  g_sum);
    cudaGetSymbolAddress((void**)&gu,   g_gu);
    cudaGetSymbolAddress((void**)&ah,   g_ah);
    cudaGetSymbolAddress((void**)&al,   g_al);
    cudaGetSymbolAddress((void**)&ctxh, g_ctxh);
    cudaGetSymbolAddress((void**)&ctxl, g_ctxl);
    cudaGetSymbolAddress((void**)&hh,   g_hh);
    cudaGetSymbolAddress((void**)&hl,   g_hl);
    cudaGetSymbolAddress((void**)&wqkvh, g_wqkvh);
    cudaGetSymbolAddress((void**)&wqkvl, g_wqkvl);
    cudaGetSymbolAddress((void**)&woh,  g_woh);
    cudaGetSymbolAddress((void**)&wol,  g_wol);
    cudaGetSymbolAddress((void**)&wguh, g_wguh);
    cudaGetSymbolAddress((void**)&wgul, g_wgul);
    cudaGetSymbolAddress((void**)&wdh,  g_wdh);
    cudaGetSymbolAddress((void**)&wdl,  g_wdl);

    cudaFuncSetAttribute(gemm_mma, cudaFuncAttributeMaxDynamicSharedMemorySize, GEMM_SMEM);
    cudaFuncSetAttribute(attn_k,   cudaFuncAttributeMaxDynamicSharedMemorySize, ATTN_SMEM_BYTES);

    // weight transpose + split (wq|wk|wv fused rows; wgate|wup fused rows)
    wconv_k<<<dim3(64, 64),  256>>>(wq, wqkvh,               wqkvl,               HIDDEN, HIDDEN);
    wconv_k<<<dim3(16, 64),  256>>>(wk, wqkvh + 2048*HIDDEN, wqkvl + 2048*HIDDEN, HIDDEN, 512);
    wconv_k<<<dim3(16, 64),  256>>>(wv, wqkvh + 2560*HIDDEN, wqkvl + 2560*HIDDEN, HIDDEN, 512);
    wconv_k<<<dim3(64, 64),  256>>>(wo, woh,                 wol,                 HIDDEN, HIDDEN);
    wconv_k<<<dim3(256, 64), 256>>>(wg, wguh,                wgul,                HIDDEN, FFN);
    wconv_k<<<dim3(256, 64), 256>>>(wu, wguh + 8192*HIDDEN,  wgul + 8192*HIDDEN,  HIDDEN, FFN);
    wconv_k<<<dim3(64, 256), 256>>>(wd, wdh,                 wdl,                 FFN,    HIDDEN);

    // norm1 -> bf16 split
    rmsnorm_bf16<<<NTOK, 256>>>(hidden, n1, ah, al);
    // fused QKV GEMM
    gemm_mma<<<dim3(QKV_DIM/128, NTOK/128), 256, GEMM_SMEM>>>(ah, al, wqkvh, wqkvl, qkv, HIDDEN, QKV_DIM, 0, nullptr, nullptr);
    // RoPE + attention
    rope_k<<<(NTOK*32 + 255)/256, 256>>>(qkv, pos);
    attn_k<<<dim3(SEQ/64, BATCH*N_HEADS), 256, ATTN_SMEM_BYTES>>>(qkv, ctx);
    // ctx -> bf16 split, O proj (+residual into sum)
    conv_bf16<<<(NTOK*HIDDEN/4 + 255)/256, 256>>>(ctx, ctxh, ctxl, NTOK*HIDDEN);
    gemm_mma<<<dim3(HIDDEN/128, NTOK/128), 256, GEMM_SMEM>>>(ctxh, ctxl, woh, wol, attn, HIDDEN, HIDDEN, 1, sum, (float*)hidden);
    // norm2 -> bf16 split
    rmsnorm_bf16<<<NTOK, 256>>>(sum, n2, ah, al);
    // fused gate|up GEMM, then silu-mul -> bf16 split
    gemm_mma<<<dim3(GU_DIM/128, NTOK/128), 256, GEMM_SMEM>>>(ah, al, wguh, wgul, gu, HIDDEN, GU_DIM, 0, nullptr, nullptr);
    silumul_k<<<(NTOK*FFN/4 + 255)/256, 256>>>(gu, hh, hl);
    // down proj (+attn) -> out
    gemm_mma<<<dim3(HIDDEN/128, NTOK/128), 256, GEMM_SMEM>>>(hh, hl, wdh, wdl, out, FFN, HIDDEN, 2, nullptr, attn);
}